// round 17
// baseline (speedup 1.0000x reference)
#include <cuda_runtime.h>
#include <cuda_bf16.h>
#include <cstdint>
#include <cstddef>

#define NH 16
#define DK 64
#define DV 64
#define DM 1024
#define BB 2
#define SS 2048

#define HB   (NH * BB)            // 32
#define ROWS (BB * SS)            // 4096
#define OUT_E (ROWS * DM)         // 4,194,304 floats
#define ATT_E ((size_t)HB * SS * SS) // 134,217,728 floats

// ---------------- scratch (no allocations allowed) ----------------
__device__ int   g_mask[ROWS];
// bf16 hi/lo q/k/v (written by proj_mma)
__device__ __nv_bfloat16 g_qh[HB * SS * DK];
__device__ __nv_bfloat16 g_ql[HB * SS * DK];
__device__ __nv_bfloat16 g_kh[HB * SS * DK];
__device__ __nv_bfloat16 g_kl[HB * SS * DK];
__device__ __nv_bfloat16 g_vh[HB * SS * DV];
__device__ __nv_bfloat16 g_vl[HB * SS * DV];
// int8 2-limb q/k (written by quant_kernel) + per-row scales
__device__ char  g_q8h[HB * SS * DK];
__device__ char  g_q8l[HB * SS * DK];
__device__ char  g_k8h[HB * SS * DK];
__device__ char  g_k8l[HB * SS * DK];
__device__ float g_qs[HB * SS];
__device__ float g_ks[HB * SS];
// bf16 hi/lo GEMM operands
__device__ __nv_bfloat16 g_xh[3][ROWS * DM];
__device__ __nv_bfloat16 g_xl[3][ROWS * DM];
__device__ __nv_bfloat16 g_wph[3][NH * DM * DK];
__device__ __nv_bfloat16 g_wpl[3][NH * DM * DK];
__device__ __nv_bfloat16 g_woh[DM * DM];
__device__ __nv_bfloat16 g_wol[DM * DM];
__device__ __nv_bfloat16 g_preh[ROWS * NH * DV];
__device__ __nv_bfloat16 g_prel[ROWS * NH * DV];

// ================= portable PTX helpers (sm_80+ ISA) ==========
__device__ __forceinline__ uint32_t smem_u32(const void* p) {
    uint32_t a;
    asm("{ .reg .u64 t; cvta.to.shared.u64 t, %1; cvt.u32.u64 %0, t; }" : "=r"(a) : "l"(p));
    return a;
}
__device__ __forceinline__ void ldm_x4(uint32_t (&r)[4], uint32_t addr) {
    asm volatile("ldmatrix.sync.aligned.m8n8.x4.shared.b16 {%0,%1,%2,%3}, [%4];"
        : "=r"(r[0]), "=r"(r[1]), "=r"(r[2]), "=r"(r[3]) : "r"(addr));
}
__device__ __forceinline__ void ldm_x2(uint32_t (&r)[2], uint32_t addr) {
    asm volatile("ldmatrix.sync.aligned.m8n8.x2.shared.b16 {%0,%1}, [%2];"
        : "=r"(r[0]), "=r"(r[1]) : "r"(addr));
}
__device__ __forceinline__ void ldm_x2_trans(uint32_t (&r)[2], uint32_t addr) {
    asm volatile("ldmatrix.sync.aligned.m8n8.x2.trans.shared.b16 {%0,%1}, [%2];"
        : "=r"(r[0]), "=r"(r[1]) : "r"(addr));
}
__device__ __forceinline__ void mma16816(float (&d)[4], const uint32_t (&a)[4], const uint32_t (&b)[2]) {
    asm volatile("mma.sync.aligned.m16n8k16.row.col.f32.bf16.bf16.f32 "
        "{%0,%1,%2,%3}, {%4,%5,%6,%7}, {%8,%9}, {%0,%1,%2,%3};"
        : "+f"(d[0]), "+f"(d[1]), "+f"(d[2]), "+f"(d[3])
        : "r"(a[0]), "r"(a[1]), "r"(a[2]), "r"(a[3]), "r"(b[0]), "r"(b[1]));
}
// int8 MMA: D(16x8,s32) += A(16x32,s8) * B(32x8,s8)
__device__ __forceinline__ void mma_s8(int (&d)[4], const uint32_t (&a)[4], const uint32_t (&b)[2]) {
    asm volatile("mma.sync.aligned.m16n8k32.row.col.s32.s8.s8.s32 "
        "{%0,%1,%2,%3}, {%4,%5,%6,%7}, {%8,%9}, {%0,%1,%2,%3};"
        : "+r"(d[0]), "+r"(d[1]), "+r"(d[2]), "+r"(d[3])
        : "r"(a[0]), "r"(a[1]), "r"(a[2]), "r"(a[3]), "r"(b[0]), "r"(b[1]));
}
__device__ __forceinline__ uint32_t bf2_bits(__nv_bfloat162 v) {
    return *reinterpret_cast<uint32_t*>(&v);
}
#define CP_ASYNC16(dst, src) \
    asm volatile("cp.async.cg.shared.global [%0], [%1], 16;" :: "r"(dst), "l"(src))
#define CP_COMMIT() asm volatile("cp.async.commit_group;" ::: "memory")
#define CP_WAIT1() asm volatile("cp.async.wait_group 1;" ::: "memory")
#define CP_WAIT0() asm volatile("cp.async.wait_group 0;" ::: "memory")

// ---------------- mask conversion (dtype-robust) ----------------
__global__ void mask_kernel(const void* mraw, int n) {
    __shared__ int mode;
    if (threadIdx.x == 0) {
        const unsigned* mi = (const unsigned*)mraw;
        const float* mf = (const float*)mraw;
        int lim = n / 4; if (lim > 1024) lim = 1024;
        int ok_i = 1, ok_f = 1;
        for (int i = 0; i < lim; i++) {
            if (mi[i] > 1u) ok_i = 0;
            float f = mf[i];
            if (!(f == 0.0f || f == 1.0f)) ok_f = 0;
            if (!ok_i && !ok_f) break;
        }
        mode = ok_i ? 1 : (ok_f ? 2 : 0);
    }
    __syncthreads();
    int md = mode;
    for (int i = threadIdx.x; i < n; i += blockDim.x) {
        int val;
        if (md == 1)      val = ((const int*)mraw)[i] != 0;
        else if (md == 2) val = ((const float*)mraw)[i] != 0.0f;
        else              val = ((const unsigned char*)mraw)[i] != 0;
        g_mask[i] = val;
    }
}

// ---------------- fp32 -> bf16 hi/lo conversion ----------------
__global__ __launch_bounds__(256) void cvt_kernel(const float* __restrict__ in,
                                                  __nv_bfloat16* __restrict__ oh,
                                                  __nv_bfloat16* __restrict__ ol, int n4) {
    int i = blockIdx.x * blockDim.x + threadIdx.x;
    if (i >= n4) return;
    float4 f = ((const float4*)in)[i];
    __nv_bfloat162 h0 = __floats2bfloat162_rn(f.x, f.y);
    __nv_bfloat162 h1 = __floats2bfloat162_rn(f.z, f.w);
    __nv_bfloat162 l0 = __floats2bfloat162_rn(f.x - __low2float(h0), f.y - __high2float(h0));
    __nv_bfloat162 l1 = __floats2bfloat162_rn(f.z - __low2float(h1), f.w - __high2float(h1));
    ((uint2*)oh)[i] = make_uint2(bf2_bits(h0), bf2_bits(h1));
    ((uint2*)ol)[i] = make_uint2(bf2_bits(l0), bf2_bits(l1));
}

// ---------------- q/k int8 2-limb quantization (warp per row of 64) ----------------
__global__ __launch_bounds__(256) void quant_kernel() {
    const int row = blockIdx.x * 8 + (threadIdx.x >> 5);
    const int lane = threadIdx.x & 31;
    const __nv_bfloat16 *sh, *sl; char *dh, *dl; float* ds;
    if (blockIdx.y == 0) { sh = g_qh; sl = g_ql; dh = g_q8h; dl = g_q8l; ds = g_qs; }
    else                 { sh = g_kh; sl = g_kl; dh = g_k8h; dl = g_k8l; ds = g_ks; }
    size_t base = (size_t)row * 64 + lane * 2;
    __nv_bfloat162 h2 = *(const __nv_bfloat162*)(sh + base);
    __nv_bfloat162 l2 = *(const __nv_bfloat162*)(sl + base);
    float x0 = __low2float(h2) + __low2float(l2);
    float x1 = __high2float(h2) + __high2float(l2);
    float m = fmaxf(fabsf(x0), fabsf(x1));
#pragma unroll
    for (int o = 16; o; o >>= 1) m = fmaxf(m, __shfl_xor_sync(0xffffffffu, m, o));
    m = fmaxf(m * 1.01f, 1e-20f);
    float inv = 16384.0f / m;
    float q0 = rintf(x0 * inv), q1 = rintf(x1 * inv);
    float h0 = rintf(q0 * (1.0f / 128.0f)), h1 = rintf(q1 * (1.0f / 128.0f));
    float lo0 = q0 - 128.0f * h0, lo1 = q1 - 128.0f * h1;
    *(char2*)(dh + base) = make_char2((char)(int)h0, (char)(int)h1);
    *(char2*)(dl + base) = make_char2((char)(int)lo0, (char)(int)lo1);
    if (lane == 0) ds[row] = m * (1.0f / 16384.0f);
}

// ---------------- mma GEMM tiles: 64x64 C, 8 warps ------
#define ROW_B 144
#define SXH 0
#define SXL 9216
#define SWH 18432
#define SWL 27648

__global__ void __launch_bounds__(256) proj_mma_kernel(const __nv_bfloat16* __restrict__ Xh,
                                                       const __nv_bfloat16* __restrict__ Xl,
                                                       const __nv_bfloat16* __restrict__ Wh,
                                                       const __nv_bfloat16* __restrict__ Wl,
                                                       __nv_bfloat16* __restrict__ Chi,
                                                       __nv_bfloat16* __restrict__ Clo) {
    __shared__ char sm[4 * 64 * ROW_B];
    uint32_t sb = smem_u32(sm);
    const int tid = threadIdx.x, lane = tid & 31, wid = tid >> 5;
    const int mw = wid & 3, nw = wid >> 2;
    const int h = blockIdx.y;
    const int m0 = blockIdx.x * 64;
    const char* xh_g = (const char*)(Xh + (size_t)m0 * DM);
    const char* xl_g = (const char*)(Xl + (size_t)m0 * DM);
    const char* wh_g = (const char*)(Wh + (size_t)h * DM * DK);
    const char* wl_g = (const char*)(Wl + (size_t)h * DM * DK);

    float acc[4][4] = {};
    for (int k0 = 0; k0 < DM; k0 += 64) {
#pragma unroll
        for (int it = 0; it < 2; it++) {
            int i = tid + it * 256;
            int r = i >> 3, ch = (i & 7) * 16;
            size_t xo = (size_t)r * (DM * 2) + (size_t)k0 * 2 + ch;
            size_t wo = (size_t)(k0 + r) * (DK * 2) + ch;
            *(uint4*)(sm + SXH + r * ROW_B + ch) = *(const uint4*)(xh_g + xo);
            *(uint4*)(sm + SXL + r * ROW_B + ch) = *(const uint4*)(xl_g + xo);
            *(uint4*)(sm + SWH + r * ROW_B + ch) = *(const uint4*)(wh_g + wo);
            *(uint4*)(sm + SWL + r * ROW_B + ch) = *(const uint4*)(wl_g + wo);
        }
        __syncthreads();
        const int l16 = lane & 15;
#pragma unroll
        for (int ks = 0; ks < 4; ks++) {
            uint32_t ah[4], al[4];
            uint32_t aoff = (uint32_t)(mw * 16 + l16) * ROW_B + (uint32_t)(lane >> 4) * 16 + ks * 32;
            ldm_x4(ah, sb + SXH + aoff);
            ldm_x4(al, sb + SXL + aoff);
            uint32_t broff = (uint32_t)(ks * 16 + l16) * ROW_B;
#pragma unroll
            for (int nt = 0; nt < 4; nt++) {
                uint32_t co = broff + (uint32_t)(nw * 32 + nt * 8) * 2;
                uint32_t bh[2], bl[2];
                ldm_x2_trans(bh, sb + SWH + co);
                ldm_x2_trans(bl, sb + SWL + co);
                mma16816(acc[nt], ah, bh);
                mma16816(acc[nt], al, bh);
                mma16816(acc[nt], ah, bl);
            }
        }
        __syncthreads();
    }
    const int b = m0 / SS;
    const int s0 = m0 - b * SS;
    const int hb = h * BB + b;
    const int g = lane >> 2, qq = (lane & 3) * 2;
    size_t row0 = ((size_t)hb * SS + s0 + mw * 16 + g) * DK;
    size_t row1 = row0 + 8 * DK;
#pragma unroll
    for (int nt = 0; nt < 4; nt++) {
        int c = nw * 32 + nt * 8 + qq;
        __nv_bfloat162 h0 = __floats2bfloat162_rn(acc[nt][0], acc[nt][1]);
        __nv_bfloat162 l0 = __floats2bfloat162_rn(acc[nt][0] - __low2float(h0),
                                                  acc[nt][1] - __high2float(h0));
        __nv_bfloat162 h1 = __floats2bfloat162_rn(acc[nt][2], acc[nt][3]);
        __nv_bfloat162 l1 = __floats2bfloat162_rn(acc[nt][2] - __low2float(h1),
                                                  acc[nt][3] - __high2float(h1));
        *(uint32_t*)(Chi + row0 + c) = bf2_bits(h0);
        *(uint32_t*)(Clo + row0 + c) = bf2_bits(l0);
        *(uint32_t*)(Chi + row1 + c) = bf2_bits(h1);
        *(uint32_t*)(Clo + row1 + c) = bf2_bits(l1);
    }
}

__global__ void __launch_bounds__(256) outgemm_mma_kernel(float* __restrict__ out) {
    __shared__ char sm[4 * 64 * ROW_B];
    uint32_t sb = smem_u32(sm);
    const int tid = threadIdx.x, lane = tid & 31, wid = tid >> 5;
    const int mw = wid & 3, nw = wid >> 2;
    const int m0 = blockIdx.x * 64;
    const int n0 = blockIdx.y * 64;
    const char* ah_g = (const char*)(g_preh + (size_t)m0 * DM);
    const char* al_g = (const char*)(g_prel + (size_t)m0 * DM);
    const char* bh_g = (const char*)g_woh;
    const char* bl_g = (const char*)g_wol;

    float acc[4][4] = {};
    for (int k0 = 0; k0 < DM; k0 += 64) {
#pragma unroll
        for (int it = 0; it < 2; it++) {
            int i = tid + it * 256;
            int r = i >> 3, ch = (i & 7) * 16;
            size_t ao = (size_t)r * (DM * 2) + (size_t)k0 * 2 + ch;
            size_t bo = (size_t)(k0 + r) * (DM * 2) + (size_t)n0 * 2 + ch;
            *(uint4*)(sm + SXH + r * ROW_B + ch) = *(const uint4*)(ah_g + ao);
            *(uint4*)(sm + SXL + r * ROW_B + ch) = *(const uint4*)(al_g + ao);
            *(uint4*)(sm + SWH + r * ROW_B + ch) = *(const uint4*)(bh_g + bo);
            *(uint4*)(sm + SWL + r * ROW_B + ch) = *(const uint4*)(bl_g + bo);
        }
        __syncthreads();
        const int l16 = lane & 15;
#pragma unroll
        for (int ks = 0; ks < 4; ks++) {
            uint32_t ah[4], al[4];
            uint32_t aoff = (uint32_t)(mw * 16 + l16) * ROW_B + (uint32_t)(lane >> 4) * 16 + ks * 32;
            ldm_x4(ah, sb + SXH + aoff);
            ldm_x4(al, sb + SXL + aoff);
            uint32_t broff = (uint32_t)(ks * 16 + l16) * ROW_B;
#pragma unroll
            for (int nt = 0; nt < 4; nt++) {
                uint32_t co = broff + (uint32_t)(nw * 32 + nt * 8) * 2;
                uint32_t bh[2], bl[2];
                ldm_x2_trans(bh, sb + SWH + co);
                ldm_x2_trans(bl, sb + SWL + co);
                mma16816(acc[nt], ah, bh);
                mma16816(acc[nt], al, bh);
                mma16816(acc[nt], ah, bl);
            }
        }
        __syncthreads();
    }
    const int g = lane >> 2, qq = (lane & 3) * 2;
    float* c0 = out + (size_t)(m0 + mw * 16 + g) * DM + n0;
    float* c1 = c0 + 8 * DM;
#pragma unroll
    for (int nt = 0; nt < 4; nt++) {
        int c = nw * 32 + nt * 8 + qq;
        *(float2*)(c0 + c) = make_float2(acc[nt][0], acc[nt][1]);
        *(float2*)(c1 + c) = make_float2(acc[nt][2], acc[nt][3]);
    }
}

// ---------------- attention: int8 QK + bf16 PV + fused norm ----------------
#define K8RB 80
#define SM_Q8H 0
#define SM_Q8L 5120
#define SM_KV 10240
#define STG_B 28928          // K8H 0, K8L 5120, VH 10240, VL 19456, KSC 28672
#define SM_MSK2 68096        // 2048 ints
#define SM_ROWSUM 76288
#define SM_INV 76800
#define ATTN_SMEM 77056

__device__ __forceinline__ void prefetch_kv(uint32_t stg, const char* k8h, const char* k8l,
                                            const char* vh, const char* vl,
                                            const char* ksc, int tid) {
    // k int8 tiles: 64 rows x 64B
    {
        int r = tid >> 2, ch = (tid & 3) * 16;
        uint32_t doff = (uint32_t)r * K8RB + ch;
        uint32_t soff = (uint32_t)r * 64 + ch;
        CP_ASYNC16(stg + 0    + doff, k8h + soff);
        CP_ASYNC16(stg + 5120 + doff, k8l + soff);
    }
    // v bf16 tiles: 64 rows x 128B
#pragma unroll
    for (int j = 0; j < 2; j++) {
        int c = tid + j * 256;
        int r = c >> 3, ch = (c & 7) * 16;
        uint32_t doff = (uint32_t)r * ROW_B + ch;
        uint32_t soff = (uint32_t)r * 128 + ch;
        CP_ASYNC16(stg + 10240 + doff, vh + soff);
        CP_ASYNC16(stg + 19456 + doff, vl + soff);
    }
    // k scales: 64 f32 = 256B
    if (tid < 16) CP_ASYNC16(stg + 28672 + tid * 16, ksc + tid * 16);
}

__global__ void __launch_bounds__(256) attn_mma_kernel(float* __restrict__ attn) {
    extern __shared__ char sm[];
    uint32_t sb = smem_u32(sm);
    const int tid = threadIdx.x, lane = tid & 31, wid = tid >> 5;
    const int mw = wid & 3, nw = wid >> 2;
    const int hh = blockIdx.z, b = blockIdx.y;
    const int q0 = blockIdx.x * 64;
    const int hb = hh * BB + b;

    // Q int8 tiles + mask row (plain loads, once)
    {
        const char* q8h_g = g_q8h + ((size_t)hb * SS + q0) * DK;
        const char* q8l_g = g_q8l + ((size_t)hb * SS + q0) * DK;
        int r = tid >> 2, ch = (tid & 3) * 16;
        *(uint4*)(sm + SM_Q8H + r * K8RB + ch) = *(const uint4*)(q8h_g + r * 64 + ch);
        *(uint4*)(sm + SM_Q8L + r * K8RB + ch) = *(const uint4*)(q8l_g + r * 64 + ch);
        const int4* mg = (const int4*)(g_mask + b * SS);
#pragma unroll
        for (int j = 0; j < 2; j++)
            ((int4*)(sm + SM_MSK2))[tid + j * 256] = mg[tid + j * 256];
    }

    const char* k8h_g = g_k8h + (size_t)hb * SS * DK;
    const char* k8l_g = g_k8l + (size_t)hb * SS * DK;
    const char* vh_g = (const char*)(g_vh + (size_t)hb * SS * DV);
    const char* vl_g = (const char*)(g_vl + (size_t)hb * SS * DV);
    const char* ksc_g = (const char*)(g_ks + (size_t)hb * SS);

    prefetch_kv(sb + SM_KV, k8h_g, k8l_g, vh_g, vl_g, ksc_g, tid);
    CP_COMMIT();
    __syncthreads();

    // Q int8 A-fragments (regs for whole kernel): [limb][ks 32-chunk][4]
    uint32_t qa_h[2][4], qa_l[2][4];
    {
        uint32_t roff = (uint32_t)(mw * 16 + (lane & 15)) * K8RB + (uint32_t)(lane >> 4) * 16;
#pragma unroll
        for (int ks = 0; ks < 2; ks++) {
            ldm_x4(qa_h[ks], sb + SM_Q8H + roff + ks * 32);
            ldm_x4(qa_l[ks], sb + SM_Q8L + roff + ks * 32);
        }
    }

    const int g = lane >> 2, qq = (lane & 3) * 2;
    const int r0 = mw * 16 + g, r1 = r0 + 8;
    const float qsc0 = g_qs[(size_t)hb * SS + q0 + r0] * 0.125f;
    const float qsc1 = g_qs[(size_t)hb * SS + q0 + r1] * 0.125f;

    float oacc[8][4] = {};
    float rs0 = 0.0f, rs1 = 0.0f;
    float* arow0 = attn ? attn + ((size_t)hb * SS + q0 + r0) * SS : (float*)0;
    float* arow1 = attn ? attn + ((size_t)hb * SS + q0 + r1) * SS : (float*)0;
    const int* mskall = (const int*)(sm + SM_MSK2);

    for (int it = 0; it < SS / 64; it++) {
        const int kt = it * 64;
        if (it + 1 < SS / 64) {
            uint32_t stg2 = sb + SM_KV + ((it + 1) & 1) * STG_B;
            size_t k8off = (size_t)(kt + 64) * DK;
            size_t voff = (size_t)(kt + 64) * DV * 2;
            prefetch_kv(stg2, k8h_g + k8off, k8l_g + k8off, vh_g + voff, vl_g + voff,
                        ksc_g + (size_t)(kt + 64) * 4, tid);
            CP_COMMIT();
            CP_WAIT1();
        } else {
            CP_WAIT0();
        }
        __syncthreads();
        const uint32_t stg = sb + SM_KV + (it & 1) * STG_B;

        // ---- scores: int8 3-pass (HH, HL+LH), exact s32 accumulation ----
        int hhacc[4][4] = {};
        int mmacc[4][4] = {};
        {
            const int l16 = lane & 15;
#pragma unroll
            for (int nt = 0; nt < 4; nt++) {
                uint32_t ro = (uint32_t)(nw * 32 + nt * 8 + (l16 & 7)) * K8RB
                            + (uint32_t)((l16 >> 3) & 1) * 16;
#pragma unroll
                for (int ks = 0; ks < 2; ks++) {
                    uint32_t co = ro + ks * 32;
                    uint32_t bh[2], bl[2];
                    ldm_x2(bh, stg + 0 + co);
                    ldm_x2(bl, stg + 5120 + co);
                    mma_s8(hhacc[nt], qa_h[ks], bh);
                    mma_s8(mmacc[nt], qa_h[ks], bl);
                    mma_s8(mmacc[nt], qa_l[ks], bh);
                }
            }
        }

        // ---- epilogue: dequant + mask + exp + attn store + rowsum + P hi/lo frags ----
        uint32_t ph[4][2], pl[4][2];
#pragma unroll
        for (int nt = 0; nt < 4; nt++) {
            int cb = nw * 32 + nt * 8 + qq;
            float ksc0 = *(const float*)(sm + (stg - sb) + 28672 + cb * 4);
            float ksc1 = *(const float*)(sm + (stg - sb) + 28672 + (cb + 1) * 4);
            float f00 = fmaf(16384.0f, (float)hhacc[nt][0], 128.0f * (float)mmacc[nt][0]);
            float f01 = fmaf(16384.0f, (float)hhacc[nt][1], 128.0f * (float)mmacc[nt][1]);
            float f10 = fmaf(16384.0f, (float)hhacc[nt][2], 128.0f * (float)mmacc[nt][2]);
            float f11 = fmaf(16384.0f, (float)hhacc[nt][3], 128.0f * (float)mmacc[nt][3]);
            int m0 = mskall[kt + cb], m1 = mskall[kt + cb + 1];
            float e00 = m0 ? __expf(f00 * qsc0 * ksc0) : 0.0f;
            float e01 = m1 ? __expf(f01 * qsc0 * ksc1) : 0.0f;
            float e10 = m0 ? __expf(f10 * qsc1 * ksc0) : 0.0f;
            float e11 = m1 ? __expf(f11 * qsc1 * ksc1) : 0.0f;
            rs0 += e00 + e01; rs1 += e10 + e11;
            if (arow0) {
                *(float2*)(arow0 + kt + cb) = make_float2(e00, e01);
                *(float2*)(arow1 + kt + cb) = make_float2(e10, e11);
            }
            __nv_bfloat162 h0 = __floats2bfloat162_rn(e00, e01);
            __nv_bfloat162 h1 = __floats2bfloat162_rn(e10, e11);
            __nv_bfloat162 l0 = __floats2bfloat162_rn(e00 - __low2float(h0), e01 - __high2float(h0));
            __nv_bfloat162 l1 = __floats2bfloat162_rn(e10 - __low2float(h1), e11 - __high2float(h1));
            ph[nt][0] = bf2_bits(h0); ph[nt][1] = bf2_bits(h1);
            pl[nt][0] = bf2_bits(l0); pl[nt][1] = bf2_bits(l1);
        }

        // ---- PV: O += P V (bf16 3-pass, proven) ----
        {
            const int l16 = lane & 15;
#pragma unroll
            for (int ks = 0; ks < 2; ks++) {
                uint32_t ah[4] = {ph[2*ks][0], ph[2*ks][1], ph[2*ks+1][0], ph[2*ks+1][1]};
                uint32_t al[4] = {pl[2*ks][0], pl[2*ks][1], pl[2*ks+1][0], pl[2*ks+1][1]};
                uint32_t roff = (uint32_t)(nw * 32 + ks * 16 + l16) * ROW_B;
#pragma unroll
                for (int vt = 0; vt < 8; vt++) {
                    uint32_t co = roff + vt * 16;
                    uint32_t bh[2], bl[2];
                    ldm_x2_trans(bh, stg + 10240 + co);
                    ldm_x2_trans(bl, stg + 19456 + co);
                    mma16816(oacc[vt], ah, bh);
                    mma16816(oacc[vt], al, bh);
                    mma16816(oacc[vt], ah, bl);
                }
            }
        }
        __syncthreads();
    }

    // ---- rowsum reduction + O exchange + normalized hi/lo pre store ----
    rs0 += __shfl_xor_sync(0xffffffffu, rs0, 1);
    rs0 += __shfl_xor_sync(0xffffffffu, rs0, 2);
    rs1 += __shfl_xor_sync(0xffffffffu, rs1, 1);
    rs1 += __shfl_xor_sync(0xffffffffu, rs1, 2);
    float* rowsum = (float*)(sm + SM_ROWSUM);
    if ((lane & 3) == 0) {
        rowsum[nw * 64 + r0] = rs0;
        rowsum[nw * 64 + r1] = rs1;
    }
    float* osh = (float*)(sm + SM_KV);
    if (nw == 1) {
#pragma unroll
        for (int vt = 0; vt < 8; vt++) {
            int c = vt * 8 + qq;
            *(float2*)(osh + r0 * 64 + c) = make_float2(oacc[vt][0], oacc[vt][1]);
            *(float2*)(osh + r1 * 64 + c) = make_float2(oacc[vt][2], oacc[vt][3]);
        }
    }
    __syncthreads();
    float* invrow = (float*)(sm + SM_INV);
    if (tid < 64) {
        float t = rowsum[tid] + rowsum[64 + tid];
        invrow[tid] = (t > 0.0f) ? (1.0f / t) : 0.0f;
    }
    __syncthreads();
    if (nw == 0) {
        float iv0 = invrow[r0], iv1 = invrow[r1];
        size_t p0 = ((size_t)(b * SS + q0 + r0)) * (NH * DV) + hh * DV;
        size_t p1 = ((size_t)(b * SS + q0 + r1)) * (NH * DV) + hh * DV;
#pragma unroll
        for (int vt = 0; vt < 8; vt++) {
            int c = vt * 8 + qq;
            float2 t0 = *(float2*)(osh + r0 * 64 + c);
            float2 t1 = *(float2*)(osh + r1 * 64 + c);
            float f00 = (oacc[vt][0] + t0.x) * iv0, f01 = (oacc[vt][1] + t0.y) * iv0;
            float f10 = (oacc[vt][2] + t1.x) * iv1, f11 = (oacc[vt][3] + t1.y) * iv1;
            __nv_bfloat162 h0 = __floats2bfloat162_rn(f00, f01);
            __nv_bfloat162 l0 = __floats2bfloat162_rn(f00 - __low2float(h0), f01 - __high2float(h0));
            __nv_bfloat162 h1 = __floats2bfloat162_rn(f10, f11);
            __nv_bfloat162 l1 = __floats2bfloat162_rn(f10 - __low2float(h1), f11 - __high2float(h1));
            *(uint32_t*)(g_preh + p0 + c) = bf2_bits(h0);
            *(uint32_t*)(g_prel + p0 + c) = bf2_bits(l0);
            *(uint32_t*)(g_preh + p1 + c) = bf2_bits(h1);
            *(uint32_t*)(g_prel + p1 + c) = bf2_bits(l1);
        }
    }

    // ---- fused attn normalization (block rescales its own 64x2048 slab) ----
    if (attn) {
        float4* ab = (float4*)(attn + ((size_t)hb * SS + q0) * SS);
#pragma unroll 4
        for (int i2 = 0; i2 < 128; i2++) {
            int idx = tid + i2 * 256;
            int row = idx >> 9, col = idx & 511;
            float iv = invrow[row];
            float4 v = ab[row * 512 + col];
            v.x *= iv; v.y *= iv; v.z *= iv; v.w *= iv;
            ab[row * 512 + col] = v;
        }
    }
}

// ---------------- launch ----------------
extern "C" void kernel_launch(void* const* d_in, const int* in_sizes, int n_in,
                              void* d_out, int out_size) {
    const float* Q   = (const float*)d_in[0];
    const float* K   = (const float*)d_in[1];
    const float* V   = (const float*)d_in[2];
    const float* Wq  = (const float*)d_in[3];
    const float* Wk  = (const float*)d_in[4];
    const float* Wv  = (const float*)d_in[5];
    const float* Wo  = (const float*)d_in[6];
    const void*  msk = d_in[7];

    float* out = (float*)d_out;
    float* attn = nullptr;
    if ((size_t)out_size >= (size_t)OUT_E + ATT_E) attn = out + OUT_E;

    __nv_bfloat16 *qh, *ql, *kh, *kl, *vh, *vl, *xh, *xl, *wph, *wpl, *woh, *wol;
    cudaGetSymbolAddress((void**)&qh, g_qh);
    cudaGetSymbolAddress((void**)&ql, g_ql);
    cudaGetSymbolAddress((void**)&kh, g_kh);
    cudaGetSymbolAddress((void**)&kl, g_kl);
    cudaGetSymbolAddress((void**)&vh, g_vh);
    cudaGetSymbolAddress((void**)&vl, g_vl);
    cudaGetSymbolAddress((void**)&xh, g_xh);
    cudaGetSymbolAddress((void**)&xl, g_xl);
    cudaGetSymbolAddress((void**)&wph, g_wph);
    cudaGetSymbolAddress((void**)&wpl, g_wpl);
    cudaGetSymbolAddress((void**)&woh, g_woh);
    cudaGetSymbolAddress((void**)&wol, g_wol);

    cudaFuncSetAttribute(attn_mma_kernel, cudaFuncAttributeMaxDynamicSharedMemorySize, ATTN_SMEM);

    mask_kernel<<<1, 256>>>(msk, ROWS);

    const int X4 = ROWS * DM / 4;
    const int WP4 = NH * DM * DK / 4;
    const int WO4 = DM * DM / 4;
    cvt_kernel<<<X4 / 256, 256>>>(Q, xh + 0 * (size_t)ROWS * DM, xl + 0 * (size_t)ROWS * DM, X4);
    cvt_kernel<<<X4 / 256, 256>>>(K, xh + 1 * (size_t)ROWS * DM, xl + 1 * (size_t)ROWS * DM, X4);
    cvt_kernel<<<X4 / 256, 256>>>(V, xh + 2 * (size_t)ROWS * DM, xl + 2 * (size_t)ROWS * DM, X4);
    cvt_kernel<<<WP4 / 256, 256>>>(Wq, wph + 0 * (size_t)NH * DM * DK, wpl + 0 * (size_t)NH * DM * DK, WP4);
    cvt_kernel<<<WP4 / 256, 256>>>(Wk, wph + 1 * (size_t)NH * DM * DK, wpl + 1 * (size_t)NH * DM * DK, WP4);
    cvt_kernel<<<WP4 / 256, 256>>>(Wv, wph + 2 * (size_t)NH * DM * DK, wpl + 2 * (size_t)NH * DM * DK, WP4);
    cvt_kernel<<<WO4 / 256, 256>>>(Wo, woh, wol, WO4);

    dim3 pg(ROWS / 64, NH);
    proj_mma_kernel<<<pg, 256>>>(xh + 0 * (size_t)ROWS * DM, xl + 0 * (size_t)ROWS * DM,
                                 wph + 0 * (size_t)NH * DM * DK, wpl + 0 * (size_t)NH * DM * DK, qh, ql);
    proj_mma_kernel<<<pg, 256>>>(xh + 1 * (size_t)ROWS * DM, xl + 1 * (size_t)ROWS * DM,
                                 wph + 1 * (size_t)NH * DM * DK, wpl + 1 * (size_t)NH * DM * DK, kh, kl);
    proj_mma_kernel<<<pg, 256>>>(xh + 2 * (size_t)ROWS * DM, xl + 2 * (size_t)ROWS * DM,
                                 wph + 2 * (size_t)NH * DM * DK, wpl + 2 * (size_t)NH * DM * DK, vh, vl);

    dim3 qg(HB * SS / 8, 2);
    quant_kernel<<<qg, 256>>>();

    dim3 ag(SS / 64, BB, NH);
    attn_mma_kernel<<<ag, 256, ATTN_SMEM>>>(attn);

    dim3 og(ROWS / 64, DM / 64);
    outgemm_mma_kernel<<<og, 256>>>(out);
}